// round 1
// baseline (speedup 1.0000x reference)
#include <cuda_runtime.h>
#include <math.h>
#include <stdint.h>

#define MAXB  128
#define CAP   4096
#define NBINS 2048
#define NT    1024

// Scratch (no allocations allowed): ~4.2 MB
__device__ float g_max[MAXB];
__device__ float g_sum[MAXB];
__device__ int   g_cnt[MAXB];
__device__ float g_cval[MAXB * CAP];
__device__ int   g_cidx[MAXB * CAP];

__device__ __forceinline__ int bin_of(float x) {
    int b = (int)floorf((x + 32.0f) * 32.0f);   // bins of width 1/32 over [-32, 32]
    b = b < 0 ? 0 : b;
    return b > (NBINS - 1) ? (NBINS - 1) : b;
}

// Kernel 1: per-row max, histogram -> top-1024 threshold, sum(exp), candidate gather.
__global__ void __launch_bounds__(NT) k_stats(const float* __restrict__ logits,
                                              const float* __restrict__ temps,
                                              int V)
{
    const int row = blockIdx.x;
    const int tid = threadIdx.x;
    __shared__ int   hist[NBINS];
    __shared__ float red[NT];
    __shared__ int   s_bt, s_cnt;

    for (int i = tid; i < NBINS; i += NT) hist[i] = 0;
    __syncthreads();

    const float* lrow = logits + (size_t)row * V;

    // Pass 1: max + histogram
    float mymax = -3.402823466e38f;
    for (int i = tid; i < V; i += NT) {
        float x = lrow[i];
        mymax = fmaxf(mymax, x);
        atomicAdd(&hist[bin_of(x)], 1);
    }
    red[tid] = mymax;
    __syncthreads();
    for (int off = NT / 2; off > 0; off >>= 1) {
        if (tid < off) red[tid] = fmaxf(red[tid], red[tid + off]);
        __syncthreads();
    }
    const float mraw = red[0];
    __syncthreads();

    if (tid == 0) {
        const int need = V < 1024 ? V : 1024;
        int acc = 0, bt = 0;
        for (int b = NBINS - 1; b >= 0; b--) {
            int na = acc + hist[b];
            if (na >= need) { bt = (na <= CAP) ? b : (b + 1); break; }
            acc = na;
        }
        s_bt  = bt;
        s_cnt = 0;
    }
    __syncthreads();

    const int   bt = s_bt;
    const float T  = temps[row];
    const float m  = mraw / T;   // max(l)/T == max(l/T): division is monotone

    // Pass 2 (mostly L2 hits): sum of exp + candidate collection
    float s = 0.f;
    for (int i = tid; i < V; i += NT) {
        float x = lrow[i];
        s += expf(x / T - m);
        if (bin_of(x) >= bt) {
            int pos = atomicAdd(&s_cnt, 1);
            if (pos < CAP) {
                g_cval[row * CAP + pos] = x;
                g_cidx[row * CAP + pos] = i;
            }
        }
    }
    red[tid] = s;
    __syncthreads();   // also makes s_cnt final
    for (int off = NT / 2; off > 0; off >>= 1) {
        if (tid < off) red[tid] += red[tid + off];
        __syncthreads();
    }
    if (tid == 0) {
        g_max[row] = m;
        g_sum[row] = red[0];
        g_cnt[row] = s_cnt < CAP ? s_cnt : CAP;
    }
}

// Kernel 2: sort candidates, apply top-k/top-p/min-p exactly as reference,
// inverse-CDF sample, scatter normalized survivor probs.
__global__ void __launch_bounds__(NT) k_sample(const float* __restrict__ temps,
                                               const int*   __restrict__ top_ks,
                                               const float* __restrict__ top_ps,
                                               const float* __restrict__ min_ps,
                                               const float* __restrict__ u,
                                               float* __restrict__ out,
                                               int V, int B, int tokens_first)
{
    const int row = blockIdx.x;
    const int tid = threadIdx.x;
    __shared__ unsigned long long sk[CAP];
    __shared__ float sa[NT];
    __shared__ float sh_p0, sh_tot;

    const int C = g_cnt[row];

    // Pack keys: (orderable float bits << 32) | (~idx)  -> descending sort gives
    // descending prob with ascending-index tie-break (matches stable argsort).
    for (int i = tid; i < CAP; i += NT) {
        unsigned long long key = 0ULL;
        if (i < C) {
            unsigned fb = __float_as_uint(g_cval[row * CAP + i]);
            unsigned mu = (fb & 0x80000000u) ? ~fb : (fb | 0x80000000u);
            unsigned il = 0xFFFFFFFFu - (unsigned)g_cidx[row * CAP + i];
            key = ((unsigned long long)mu << 32) | il;
        }
        sk[i] = key;
    }
    __syncthreads();

    // Bitonic sort, descending, n = CAP (4096), 1024 threads
    for (int k = 2; k <= CAP; k <<= 1) {
        for (int j = k >> 1; j > 0; j >>= 1) {
            for (int i = tid; i < CAP; i += NT) {
                int ixj = i ^ j;
                if (ixj > i) {
                    unsigned long long a = sk[i], b = sk[ixj];
                    bool descBlock = ((i & k) == 0);
                    if (descBlock ? (a < b) : (a > b)) { sk[i] = b; sk[ixj] = a; }
                }
            }
            __syncthreads();
        }
    }

    // Per-rank probability (rank = tid, only first NT ranks ever matter)
    const float T = temps[row];
    const float m = g_max[row];
    const float S = g_sum[row];
    float p = 0.f;
    int   myidx = 0;
    if (tid < C) {
        unsigned long long key = sk[tid];
        unsigned mu = (unsigned)(key >> 32);
        unsigned fb = (mu & 0x80000000u) ? (mu ^ 0x80000000u) : ~mu;
        float x = __uint_as_float(fb) / T;
        p = expf(x - m) / S;
        myidx = (int)(0xFFFFFFFFu - (unsigned)(key & 0xFFFFFFFFu));
    }
    if (tid == 0) sh_p0 = p;

    // Inclusive scan of pre-mask sorted probs (== full-vocab cumsum at these ranks)
    sa[tid] = p;
    __syncthreads();
    for (int off = 1; off < NT; off <<= 1) {
        float v = sa[tid];
        if (tid >= off) v += sa[tid - off];
        __syncthreads();
        sa[tid] = v;
        __syncthreads();
    }
    const float cumincl = sa[tid];

    // Masks in the exact reference order
    const int   tk  = top_ks[row];
    const float tp  = top_ps[row];
    const float thr = sh_p0 * min_ps[row];
    float q = p;
    if (tid >= tk)            q = 0.f;   // top-k
    if (cumincl - q > tp)     q = 0.f;   // top-p (pre-mask cumsum minus post-top-k value)
    if (q < thr)              q = 0.f;   // min-p

    // Scan of masked probs -> CDF numerator
    __syncthreads();
    sa[tid] = q;
    __syncthreads();
    for (int off = 1; off < NT; off <<= 1) {
        float v = sa[tid];
        if (tid >= off) v += sa[tid - off];
        __syncthreads();
        sa[tid] = v;
        __syncthreads();
    }
    const float cq = sa[tid];
    if (tid == NT - 1) sh_tot = cq;
    __syncthreads();
    const float tot  = sh_tot;
    const float uval = u[row];

    // inverse-CDF: count of cdf < u (ranks past last survivor give cdf == 1.0 exactly)
    int rank = __syncthreads_count((cq / tot < uval) ? 1 : 0);
    if (rank > V - 1) rank = V - 1;

    float* probs_out = tokens_first ? (out + B) : out;
    if (tid == 0 && tokens_first) {
        unsigned long long key = sk[rank];
        int token = (int)(0xFFFFFFFFu - (unsigned)(key & 0xFFFFFFFFu));
        out[row] = (float)token;
    }
    if (q > 0.f) {
        probs_out[(size_t)row * V + myidx] = q / tot;
    }
}

extern "C" void kernel_launch(void* const* d_in, const int* in_sizes, int n_in,
                              void* d_out, int out_size)
{
    const float* logits = (const float*)d_in[0];
    const float* temps  = (const float*)d_in[1];
    const int*   topks  = (const int*)  d_in[2];
    const float* topps  = (const float*)d_in[3];
    const float* minps  = (const float*)d_in[4];
    const float* u      = (const float*)d_in[5];

    const int B = in_sizes[1];
    const int V = in_sizes[0] / B;
    float* out = (float*)d_out;

    // Layout: assume (token_ids[B], norm_probs[B*V]) concatenated as float32.
    int tokens_first = (out_size == B + B * V) ? 1 : 0;

    cudaMemsetAsync(d_out, 0, (size_t)out_size * sizeof(float), 0);
    k_stats <<<B, NT>>>(logits, temps, V);
    k_sample<<<B, NT>>>(temps, topks, topps, minps, u, out, V, B, tokens_first);
}

// round 2
// speedup vs baseline: 1.0332x; 1.0332x over previous
#include <cuda_runtime.h>
#include <math.h>
#include <stdint.h>

#define MAXB  128
#define CAP   4096
#define NBINS 2048
#define NT    1024

// Global scratch (no allocations allowed)
__device__ float g_sum[MAXB];
__device__ float g_shift[MAXB];
__device__ int   g_cnt[MAXB];
__device__ float g_cval[MAXB * CAP];
__device__ int   g_cidx[MAXB * CAP];

__device__ __forceinline__ int bin_of(float x) {
    int b = (int)floorf((x + 32.0f) * 32.0f);   // width 1/32 over [-32, 32]
    b = b < 0 ? 0 : b;
    return b > (NBINS - 1) ? (NBINS - 1) : b;
}

__device__ __forceinline__ float warp_red_sum(float v) {
    #pragma unroll
    for (int o = 16; o; o >>= 1) v += __shfl_xor_sync(0xffffffffu, v, o);
    return v;
}
__device__ __forceinline__ float warp_red_max(float v) {
    #pragma unroll
    for (int o = 16; o; o >>= 1) v = fmaxf(v, __shfl_xor_sync(0xffffffffu, v, o));
    return v;
}

// Block-wide inclusive scan over NT=1024 values (one per thread), shuffle-based.
__device__ __forceinline__ float block_incl_scan(float v, float* wsum, int lane, int wid) {
    #pragma unroll
    for (int off = 1; off < 32; off <<= 1) {
        float n = __shfl_up_sync(0xffffffffu, v, off);
        if (lane >= off) v += n;
    }
    __syncthreads();                 // protect wsum reuse across calls
    if (lane == 31) wsum[wid] = v;
    __syncthreads();
    if (wid == 0) {
        float w = wsum[lane];
        #pragma unroll
        for (int off = 1; off < 32; off <<= 1) {
            float n = __shfl_up_sync(0xffffffffu, w, off);
            if (lane >= off) w += n;
        }
        wsum[lane] = w;
    }
    __syncthreads();
    return v + (wid ? wsum[wid - 1] : 0.f);
}

// Kernel 1: per-row sum(exp(x/T)), subsample-histogram threshold, candidate gather.
__global__ void __launch_bounds__(NT) k_stats(const float* __restrict__ logits,
                                              const float* __restrict__ temps, int V)
{
    const int row = blockIdx.x;
    const int tid = threadIdx.x;
    const int lane = tid & 31, wid = tid >> 5;
    __shared__ int   hist[NBINS];
    __shared__ float wred[32];
    __shared__ float s_S, s_shift;
    __shared__ int   s_bt, s_cnt;

    const float* lrow = logits + (size_t)row * V;
    const float invT = 1.0f / temps[row];
    const int need = V < 1024 ? V : 1024;

    // ---- Phase A: one pass -> max + unshifted sum of exp (float4 loads) ----
    float s = 0.f, mx = -3.402823466e38f;
    const int V4 = V >> 2;
    const float4* l4 = (const float4*)lrow;
    for (int i = tid; i < V4; i += NT) {
        float4 v = l4[i];
        mx = fmaxf(mx, fmaxf(fmaxf(v.x, v.y), fmaxf(v.z, v.w)));
        s += expf(v.x * invT) + expf(v.y * invT) + expf(v.z * invT) + expf(v.w * invT);
    }
    for (int i = (V4 << 2) + tid; i < V; i += NT) {
        float x = lrow[i];
        mx = fmaxf(mx, x);
        s += expf(x * invT);
    }
    s = warp_red_sum(s);
    if (lane == 0) wred[wid] = s;
    __syncthreads();
    if (wid == 0) { float t = warp_red_sum(wred[lane]); if (lane == 0) s_S = t; }
    __syncthreads();
    mx = warp_red_max(mx);
    if (lane == 0) wred[wid] = mx;
    __syncthreads();
    if (wid == 0) {
        float t = warp_red_max(wred[lane]);
        if (lane == 0) {
            float mxT = t * invT;
            s_shift = (mxT > 80.f || !isfinite(s_S)) ? mxT : 0.f;
        }
    }
    __syncthreads();
    const float shift = s_shift;
    if (shift != 0.f) {            // rare overflow-safe recompute
        s = 0.f;
        for (int i = tid; i < V; i += NT) s += expf(lrow[i] * invT - shift);
        s = warp_red_sum(s);
        if (lane == 0) wred[wid] = s;
        __syncthreads();
        if (wid == 0) { float t = warp_red_sum(wred[lane]); if (lane == 0) s_S = t; }
        __syncthreads();
    }

    // ---- Phase B: subsample histogram -> candidate bin threshold ----
    if (V > CAP) {
        for (int i = tid; i < NBINS; i += NT) hist[i] = 0;
        __syncthreads();
        int stride = V / 8192; if (stride < 1) stride = 1;
        int subN = (V + stride - 1) / stride;
        for (int j = tid; j < subN; j += NT)
            atomicAdd(&hist[bin_of(lrow[(size_t)j * stride])], 1);
        __syncthreads();
        if (tid == 0) {
            // target expected true count ~ 1.8 * need (>=4.5 sigma above need)
            long long tgt = ((long long)need * 9LL * subN) / (5LL * (long long)V);
            if (tgt < 1) tgt = 1;
            int acc = 0, bt = 0;
            for (int b = NBINS - 1; b >= 0; b--) {
                acc += hist[b];
                if (acc >= tgt) { bt = b; break; }
            }
            s_bt = bt;
        }
        __syncthreads();
    }

    // ---- Phase C: gather candidates (L2-resident), verify count, rare fallback ----
    int attempt = 0, cnt = 0;
    for (;;) {
        if (V <= CAP) {
            for (int i = tid; i < V; i += NT) {
                g_cval[row * CAP + i] = lrow[i];
                g_cidx[row * CAP + i] = i;
            }
            cnt = V;
            break;
        }
        if (tid == 0) s_cnt = 0;
        __syncthreads();
        const int bt = s_bt;
        for (int i = tid; i < V; i += NT) {
            float x = lrow[i];
            if (bin_of(x) >= bt) {
                int pos = atomicAdd(&s_cnt, 1);
                if (pos < CAP) {
                    g_cval[row * CAP + pos] = x;
                    g_cidx[row * CAP + pos] = i;
                }
            }
        }
        __syncthreads();
        cnt = s_cnt;
        if ((cnt >= need && cnt <= CAP) || attempt) break;
        // FALLBACK (statistically ~never): exact full histogram, guaranteed threshold
        for (int i = tid; i < NBINS; i += NT) hist[i] = 0;
        __syncthreads();
        for (int i = tid; i < V; i += NT) atomicAdd(&hist[bin_of(lrow[i])], 1);
        __syncthreads();
        if (tid == 0) {
            int acc = 0, bt2 = 0;
            for (int b = NBINS - 1; b >= 0; b--) {
                int na = acc + hist[b];
                if (na >= need) { bt2 = (na <= CAP) ? b : (b + 1); break; }
                acc = na;
            }
            s_bt = bt2;
        }
        __syncthreads();
        attempt = 1;
    }
    if (tid == 0) {
        g_cnt[row]   = cnt < CAP ? cnt : CAP;
        g_sum[row]   = s_S;
        g_shift[row] = shift;
    }
}

// Kernel 2: sort candidates (next-pow2 size), masks in reference order, sample, scatter.
__global__ void __launch_bounds__(NT) k_sample(const float* __restrict__ temps,
                                               const int*   __restrict__ top_ks,
                                               const float* __restrict__ top_ps,
                                               const float* __restrict__ min_ps,
                                               const float* __restrict__ u,
                                               float* __restrict__ out,
                                               int V, int B, int tokens_first)
{
    const int row = blockIdx.x;
    const int tid = threadIdx.x;
    const int lane = tid & 31, wid = tid >> 5;
    __shared__ unsigned long long sk[CAP];
    __shared__ float wsum[32];
    __shared__ float sh_p0, sh_tot;

    const int C = g_cnt[row];
    int npow2 = 2; while (npow2 < C) npow2 <<= 1;

    // Pack keys: (orderable float bits << 32) | (~idx) -> descending sort ==
    // descending prob with ascending-index tie-break (stable argsort semantics).
    for (int i = tid; i < npow2; i += NT) {
        unsigned long long key = 0ULL;
        if (i < C) {
            unsigned fb = __float_as_uint(g_cval[row * CAP + i]);
            unsigned mu = (fb & 0x80000000u) ? ~fb : (fb | 0x80000000u);
            unsigned il = 0xFFFFFFFFu - (unsigned)g_cidx[row * CAP + i];
            key = ((unsigned long long)mu << 32) | il;
        }
        sk[i] = key;
    }
    __syncthreads();

    // Bitonic sort, descending, n = npow2
    for (int k = 2; k <= npow2; k <<= 1) {
        for (int j = k >> 1; j > 0; j >>= 1) {
            for (int i = tid; i < npow2; i += NT) {
                int ixj = i ^ j;
                if (ixj > i) {
                    unsigned long long a = sk[i], b = sk[ixj];
                    if (((i & k) == 0) ? (a < b) : (a > b)) { sk[i] = b; sk[ixj] = a; }
                }
            }
            __syncthreads();
        }
    }

    // Per-rank prob (only first NT ranks can ever survive: top_k < 1024)
    const float invT  = 1.0f / temps[row];
    const float S     = g_sum[row];
    const float shift = g_shift[row];
    float p = 0.f;
    int   myidx = 0;
    if (tid < C) {
        unsigned long long key = sk[tid];
        unsigned mu = (unsigned)(key >> 32);
        unsigned fb = (mu & 0x80000000u) ? (mu ^ 0x80000000u) : ~mu;
        p = expf(__uint_as_float(fb) * invT - shift) / S;
        myidx = (int)(0xFFFFFFFFu - (unsigned)(key & 0xFFFFFFFFu));
    }
    if (tid == 0) sh_p0 = p;

    // Pre-mask inclusive cumsum (== full-vocab cumsum at these ranks)
    float cumincl = block_incl_scan(p, wsum, lane, wid);

    // Masks in exact reference order
    const int   tk  = top_ks[row];
    const float tp  = top_ps[row];
    const float thr = sh_p0 * min_ps[row];
    float q = p;
    if (tid >= tk)        q = 0.f;   // top-k
    if (cumincl - q > tp) q = 0.f;   // top-p (cumsum computed pre-mask)
    if (q < thr)          q = 0.f;   // min-p

    // Post-mask cumsum -> CDF
    float cq = block_incl_scan(q, wsum, lane, wid);
    if (tid == NT - 1) sh_tot = cq;
    __syncthreads();
    const float tot  = sh_tot;
    const float uval = u[row];

    // inverse-CDF: cdf past last survivor is exactly 1.0 -> predicate false there
    int rank = __syncthreads_count((cq / tot < uval) ? 1 : 0);
    if (rank > npow2 - 1) rank = npow2 - 1;
    if (rank > V - 1) rank = V - 1;

    float* probs_out = tokens_first ? (out + B) : out;
    if (tid == 0 && tokens_first) {
        unsigned long long key = sk[rank];
        out[row] = (float)(int)(0xFFFFFFFFu - (unsigned)(key & 0xFFFFFFFFu));
    }
    if (q > 0.f) {
        probs_out[(size_t)row * V + myidx] = q / tot;
    }
}

extern "C" void kernel_launch(void* const* d_in, const int* in_sizes, int n_in,
                              void* d_out, int out_size)
{
    const float* logits = (const float*)d_in[0];
    const float* temps  = (const float*)d_in[1];
    const int*   topks  = (const int*)  d_in[2];
    const float* topps  = (const float*)d_in[3];
    const float* minps  = (const float*)d_in[4];
    const float* u      = (const float*)d_in[5];

    const int B = in_sizes[1];
    const int V = in_sizes[0] / B;
    float* out = (float*)d_out;
    int tokens_first = (out_size == B + B * V) ? 1 : 0;

    cudaMemsetAsync(d_out, 0, (size_t)out_size * sizeof(float), 0);
    k_stats <<<B, NT>>>(logits, temps, V);
    k_sample<<<B, NT>>>(temps, topks, topps, minps, u, out, V, B, tokens_first);
}

// round 3
// speedup vs baseline: 1.2632x; 1.2227x over previous
#include <cuda_runtime.h>
#include <math.h>
#include <stdint.h>

#define MAXB  128
#define CAP   4096
#define NBINS 2048
#define NT    1024

// Global scratch (no allocations allowed)
__device__ float g_sum[MAXB];
__device__ float g_shift[MAXB];
__device__ int   g_cnt[MAXB];
__device__ float g_cval[MAXB * CAP];
__device__ int   g_cidx[MAXB * CAP];

__device__ __forceinline__ int bin_of(float x) {
    int b = (int)floorf((x + 32.0f) * 32.0f);   // width 1/32 over [-32, 32]
    b = b < 0 ? 0 : b;
    return b > (NBINS - 1) ? (NBINS - 1) : b;
}

__device__ __forceinline__ float warp_red_sum(float v) {
    #pragma unroll
    for (int o = 16; o; o >>= 1) v += __shfl_xor_sync(0xffffffffu, v, o);
    return v;
}
__device__ __forceinline__ float warp_red_max(float v) {
    #pragma unroll
    for (int o = 16; o; o >>= 1) v = fmaxf(v, __shfl_xor_sync(0xffffffffu, v, o));
    return v;
}

// Block-wide inclusive scan over NT=1024 values (one per thread), shuffle-based.
__device__ __forceinline__ float block_incl_scan(float v, float* wsum, int lane, int wid) {
    #pragma unroll
    for (int off = 1; off < 32; off <<= 1) {
        float n = __shfl_up_sync(0xffffffffu, v, off);
        if (lane >= off) v += n;
    }
    __syncthreads();                 // protect wsum reuse across calls
    if (lane == 31) wsum[wid] = v;
    __syncthreads();
    if (wid == 0) {
        float w = wsum[lane];
        #pragma unroll
        for (int off = 1; off < 32; off <<= 1) {
            float n = __shfl_up_sync(0xffffffffu, w, off);
            if (lane >= off) w += n;
        }
        wsum[lane] = w;
    }
    __syncthreads();
    return v + (wid ? wsum[wid - 1] : 0.f);
}

// Kernel 1: per-row sum(exp(x/T)), subsample-histogram threshold, candidate gather.
__global__ void __launch_bounds__(NT) k_stats(const float* __restrict__ logits,
                                              const float* __restrict__ temps, int V)
{
    const int row = blockIdx.x;
    const int tid = threadIdx.x;
    const int lane = tid & 31, wid = tid >> 5;
    __shared__ int   hist[NBINS];
    __shared__ float wred[32];
    __shared__ float s_S, s_shift;
    __shared__ int   s_bt, s_cnt;

    const float* lrow = logits + (size_t)row * V;
    const float invT = 1.0f / temps[row];
    const int need = V < 1024 ? V : 1024;

    // ---- Phase A: one pass -> max + unshifted sum of exp (float4 + __expf) ----
    // S cancels in the normalized outputs; its only absolute use is the top-p
    // boundary, where __expf's ~1e-6 relative error is far below tolerance.
    float s = 0.f, mx = -3.402823466e38f;
    const int V4 = V >> 2;
    const float4* l4 = (const float4*)lrow;
    for (int i = tid; i < V4; i += NT) {
        float4 v = l4[i];
        mx = fmaxf(mx, fmaxf(fmaxf(v.x, v.y), fmaxf(v.z, v.w)));
        s += __expf(v.x * invT) + __expf(v.y * invT) + __expf(v.z * invT) + __expf(v.w * invT);
    }
    for (int i = (V4 << 2) + tid; i < V; i += NT) {
        float x = lrow[i];
        mx = fmaxf(mx, x);
        s += __expf(x * invT);
    }
    s = warp_red_sum(s);
    if (lane == 0) wred[wid] = s;
    __syncthreads();
    if (wid == 0) { float t = warp_red_sum(wred[lane]); if (lane == 0) s_S = t; }
    __syncthreads();
    mx = warp_red_max(mx);
    if (lane == 0) wred[wid] = mx;
    __syncthreads();
    if (wid == 0) {
        float t = warp_red_max(wred[lane]);
        if (lane == 0) {
            float mxT = t * invT;
            s_shift = (mxT > 80.f || !isfinite(s_S)) ? mxT : 0.f;
        }
    }
    __syncthreads();
    const float shift = s_shift;
    if (shift != 0.f) {            // rare overflow-safe recompute (precise path)
        s = 0.f;
        for (int i = tid; i < V; i += NT) s += expf(lrow[i] * invT - shift);
        s = warp_red_sum(s);
        if (lane == 0) wred[wid] = s;
        __syncthreads();
        if (wid == 0) { float t = warp_red_sum(wred[lane]); if (lane == 0) s_S = t; }
        __syncthreads();
    }

    // ---- Phase B: coalesced float4 subsample histogram -> bin threshold ----
    int subN = 0;
    if (V > CAP) {
        for (int i = tid; i < NBINS; i += NT) hist[i] = 0;
        __syncthreads();
        int step4 = V4 / 2048; if (step4 < 1) step4 = 1;
        int ns4 = V4 / step4; if (ns4 > 2048 + 64) ns4 = 2048 + 64;
        subN = ns4 * 4;
        for (int j = tid; j < ns4; j += NT) {
            float4 v = l4[(size_t)j * step4];
            atomicAdd(&hist[bin_of(v.x)], 1);
            atomicAdd(&hist[bin_of(v.y)], 1);
            atomicAdd(&hist[bin_of(v.z)], 1);
            atomicAdd(&hist[bin_of(v.w)], 1);
        }
        __syncthreads();
        if (tid == 0) {
            // target expected true count ~ 1.8 * need (>=4.5 sigma above need)
            long long tgt = ((long long)need * 9LL * subN) / (5LL * (long long)V);
            if (tgt < 1) tgt = 1;
            int acc = 0, bt = 0;
            for (int b = NBINS - 1; b >= 0; b--) {
                acc += hist[b];
                if (acc >= tgt) { bt = b; break; }
            }
            s_bt = bt;
        }
        __syncthreads();
    }

    // ---- Phase C: gather candidates (L2-resident), verify count, rare fallback ----
    int attempt = 0, cnt = 0;
    for (;;) {
        if (V <= CAP) {
            for (int i = tid; i < V; i += NT) {
                g_cval[row * CAP + i] = lrow[i];
                g_cidx[row * CAP + i] = i;
            }
            cnt = V;
            break;
        }
        if (tid == 0) s_cnt = 0;
        __syncthreads();
        const int bt = s_bt;
        for (int i = tid; i < V4; i += NT) {
            float4 v = l4[i];
            #pragma unroll
            for (int c = 0; c < 4; c++) {
                float x = (c == 0) ? v.x : (c == 1) ? v.y : (c == 2) ? v.z : v.w;
                if (bin_of(x) >= bt) {
                    int pos = atomicAdd(&s_cnt, 1);
                    if (pos < CAP) {
                        g_cval[row * CAP + pos] = x;
                        g_cidx[row * CAP + pos] = (i << 2) + c;
                    }
                }
            }
        }
        for (int i = (V4 << 2) + tid; i < V; i += NT) {
            float x = lrow[i];
            if (bin_of(x) >= bt) {
                int pos = atomicAdd(&s_cnt, 1);
                if (pos < CAP) {
                    g_cval[row * CAP + pos] = x;
                    g_cidx[row * CAP + pos] = i;
                }
            }
        }
        __syncthreads();
        cnt = s_cnt;
        if ((cnt >= need && cnt <= CAP) || attempt) break;
        // FALLBACK (statistically ~never): exact full histogram, guaranteed threshold
        for (int i = tid; i < NBINS; i += NT) hist[i] = 0;
        __syncthreads();
        for (int i = tid; i < V; i += NT) atomicAdd(&hist[bin_of(lrow[i])], 1);
        __syncthreads();
        if (tid == 0) {
            int acc = 0, bt2 = 0;
            for (int b = NBINS - 1; b >= 0; b--) {
                int na = acc + hist[b];
                if (na >= need) { bt2 = (na <= CAP) ? b : (b + 1); break; }
                acc = na;
            }
            s_bt = bt2;
        }
        __syncthreads();
        attempt = 1;
    }
    if (tid == 0) {
        g_cnt[row]   = cnt < CAP ? cnt : CAP;
        g_sum[row]   = s_S;
        g_shift[row] = shift;
    }
}

// Kernel 2: sort candidates, masks in reference order, sample, scatter.
__global__ void __launch_bounds__(NT) k_sample(const float* __restrict__ temps,
                                               const int*   __restrict__ top_ks,
                                               const float* __restrict__ top_ps,
                                               const float* __restrict__ min_ps,
                                               const float* __restrict__ u,
                                               float* __restrict__ out,
                                               int V, int B, int tokens_first)
{
    const int row = blockIdx.x;
    const int tid = threadIdx.x;
    const int lane = tid & 31, wid = tid >> 5;
    __shared__ unsigned long long sk[CAP];
    __shared__ float wsum[32];
    __shared__ float sh_p0, sh_tot;

    const int C = g_cnt[row];
    int npow2 = 1024; while (npow2 < C) npow2 <<= 1;   // C >= need -> npow2 >= 1024
    const int NCE = npow2 >> 1;                         // compare-exchanges per step

    // Pack keys: (orderable float bits << 32) | (~idx) -> descending sort ==
    // descending prob with ascending-index tie-break (stable argsort semantics).
    for (int i = tid; i < npow2; i += NT) {
        unsigned long long key = 0ULL;
        if (i < C) {
            unsigned fb = __float_as_uint(g_cval[row * CAP + i]);
            unsigned mu = (fb & 0x80000000u) ? ~fb : (fb | 0x80000000u);
            unsigned il = 0xFFFFFFFFu - (unsigned)g_cidx[row * CAP + i];
            key = ((unsigned long long)mu << 32) | il;
        }
        sk[i] = key;
    }
    __syncthreads();

    // Bitonic sort, descending. Non-divergent CE mapping; for j<=32 each warp's
    // CEs stay inside its own 64-element block -> __syncwarp only.
    for (int k = 2; k <= npow2; k <<= 1) {
        int j = k >> 1;
        for (; j >= 64; j >>= 1) {
            for (int c = tid; c < NCE; c += NT) {
                int i = ((c & ~(j - 1)) << 1) | (c & (j - 1));
                unsigned long long a = sk[i], b = sk[i + j];
                if (((i & k) == 0) ? (a < b) : (a > b)) { sk[i] = b; sk[i + j] = a; }
            }
            __syncthreads();
        }
        for (; j >= 1; j >>= 1) {
            for (int c = tid; c < NCE; c += NT) {
                int i = ((c & ~(j - 1)) << 1) | (c & (j - 1));
                unsigned long long a = sk[i], b = sk[i + j];
                if (((i & k) == 0) ? (a < b) : (a > b)) { sk[i] = b; sk[i + j] = a; }
            }
            __syncwarp();
        }
        __syncthreads();
    }

    // Per-rank prob (only first NT ranks can ever survive: top_k < 1024)
    const float invT  = 1.0f / temps[row];
    const float S     = g_sum[row];
    const float shift = g_shift[row];
    float p = 0.f;
    int   myidx = 0;
    if (tid < C) {
        unsigned long long key = sk[tid];
        unsigned mu = (unsigned)(key >> 32);
        unsigned fb = (mu & 0x80000000u) ? (mu ^ 0x80000000u) : ~mu;
        p = expf(__uint_as_float(fb) * invT - shift) / S;
        myidx = (int)(0xFFFFFFFFu - (unsigned)(key & 0xFFFFFFFFu));
    }
    if (tid == 0) sh_p0 = p;

    // Pre-mask inclusive cumsum (== full-vocab cumsum at these ranks)
    float cumincl = block_incl_scan(p, wsum, lane, wid);

    // Masks in exact reference order
    const int   tk  = top_ks[row];
    const float tp  = top_ps[row];
    const float thr = sh_p0 * min_ps[row];
    float q = p;
    if (tid >= tk)        q = 0.f;   // top-k
    if (cumincl - q > tp) q = 0.f;   // top-p (cumsum computed pre-mask)
    if (q < thr)          q = 0.f;   // min-p

    // Post-mask cumsum -> CDF
    float cq = block_incl_scan(q, wsum, lane, wid);
    if (tid == NT - 1) sh_tot = cq;
    __syncthreads();
    const float tot  = sh_tot;
    const float uval = u[row];

    // inverse-CDF: cdf past last survivor is exactly 1.0 -> predicate false there
    int rank = __syncthreads_count((cq / tot < uval) ? 1 : 0);
    if (rank > npow2 - 1) rank = npow2 - 1;
    if (rank > V - 1) rank = V - 1;

    float* probs_out = tokens_first ? (out + B) : out;
    if (tid == 0 && tokens_first) {
        unsigned long long key = sk[rank];
        out[row] = (float)(int)(0xFFFFFFFFu - (unsigned)(key & 0xFFFFFFFFu));
    }
    if (q > 0.f) {
        probs_out[(size_t)row * V + myidx] = q / tot;
    }
}

extern "C" void kernel_launch(void* const* d_in, const int* in_sizes, int n_in,
                              void* d_out, int out_size)
{
    const float* logits = (const float*)d_in[0];
    const float* temps  = (const float*)d_in[1];
    const int*   topks  = (const int*)  d_in[2];
    const float* topps  = (const float*)d_in[3];
    const float* minps  = (const float*)d_in[4];
    const float* u      = (const float*)d_in[5];

    const int B = in_sizes[1];
    const int V = in_sizes[0] / B;
    float* out = (float*)d_out;
    int tokens_first = (out_size == B + B * V) ? 1 : 0;

    cudaMemsetAsync(d_out, 0, (size_t)out_size * sizeof(float), 0);
    k_stats <<<B, NT>>>(logits, temps, V);
    k_sample<<<B, NT>>>(temps, topks, topps, minps, u, out, V, B, tokens_first);
}

// round 4
// speedup vs baseline: 1.9257x; 1.5244x over previous
#include <cuda_runtime.h>
#include <math.h>
#include <stdint.h>
#include <float.h>

#define MAXB  128
#define CAP   4096
#define NBINS 2048
#define NT    1024

// Global scratch (no allocations allowed)
__device__ float g_sum[MAXB];
__device__ float g_shift[MAXB];
__device__ int   g_cnt[MAXB];
__device__ float g_cval[MAXB * CAP];
__device__ int   g_cidx[MAXB * CAP];

__device__ __forceinline__ int bin_of(float x) {
    int b = (int)floorf((x + 32.0f) * 32.0f);   // width 1/32 over [-32, 32]
    b = b < 0 ? 0 : b;
    return b > (NBINS - 1) ? (NBINS - 1) : b;
}

__device__ __forceinline__ float warp_red_sum(float v) {
    #pragma unroll
    for (int o = 16; o; o >>= 1) v += __shfl_xor_sync(0xffffffffu, v, o);
    return v;
}
__device__ __forceinline__ float warp_red_max(float v) {
    #pragma unroll
    for (int o = 16; o; o >>= 1) v = fmaxf(v, __shfl_xor_sync(0xffffffffu, v, o));
    return v;
}

__device__ __forceinline__ float block_incl_scan(float v, float* wsum, int lane, int wid) {
    #pragma unroll
    for (int off = 1; off < 32; off <<= 1) {
        float n = __shfl_up_sync(0xffffffffu, v, off);
        if (lane >= off) v += n;
    }
    __syncthreads();
    if (lane == 31) wsum[wid] = v;
    __syncthreads();
    if (wid == 0) {
        float w = wsum[lane];
        #pragma unroll
        for (int off = 1; off < 32; off <<= 1) {
            float n = __shfl_up_sync(0xffffffffu, w, off);
            if (lane >= off) w += n;
        }
        wsum[lane] = w;
    }
    __syncthreads();
    return v + (wid ? wsum[wid - 1] : 0.f);
}

__device__ __forceinline__ int block_incl_scan_int(int v, int* wsum, int lane, int wid) {
    #pragma unroll
    for (int off = 1; off < 32; off <<= 1) {
        int n = __shfl_up_sync(0xffffffffu, v, off);
        if (lane >= off) v += n;
    }
    if (lane == 31) wsum[wid] = v;
    __syncthreads();
    if (wid == 0) {
        int w = wsum[lane];
        #pragma unroll
        for (int off = 1; off < 32; off <<= 1) {
            int n = __shfl_up_sync(0xffffffffu, w, off);
            if (lane >= off) w += n;
        }
        wsum[lane] = w;
    }
    __syncthreads();
    return v + (wid ? wsum[wid - 1] : 0);
}

// ---------------- Kernel 1: stats + candidate gather ----------------
__global__ void __launch_bounds__(NT) k_stats(const float* __restrict__ logits,
                                              const float* __restrict__ temps, int V)
{
    const int row = blockIdx.x;
    const int tid = threadIdx.x;
    const int lane = tid & 31, wid = tid >> 5;
    __shared__ int   hist[NBINS];
    __shared__ float wred[32];
    __shared__ int   iwsum[32];
    __shared__ float s_S, s_shift;
    __shared__ int   s_bt, s_cnt;

    const float* lrow = logits + (size_t)row * V;
    const float invT = 1.0f / temps[row];
    const int need = V < 1024 ? V : 1024;
    const int V4 = V >> 2;
    const float4* l4 = (const float4*)lrow;

    // ---- Phase A: max + unshifted sum of exp (2-way unroll, dual accumulators)
    float s = 0.f, s2 = 0.f, mx = -FLT_MAX;
    int i = tid;
    for (; i + NT < V4; i += 2 * NT) {
        float4 v0 = l4[i];
        float4 v1 = l4[i + NT];
        mx = fmaxf(mx, fmaxf(fmaxf(v0.x, v0.y), fmaxf(v0.z, v0.w)));
        mx = fmaxf(mx, fmaxf(fmaxf(v1.x, v1.y), fmaxf(v1.z, v1.w)));
        s  += __expf(v0.x * invT) + __expf(v0.y * invT) + __expf(v0.z * invT) + __expf(v0.w * invT);
        s2 += __expf(v1.x * invT) + __expf(v1.y * invT) + __expf(v1.z * invT) + __expf(v1.w * invT);
    }
    for (; i < V4; i += NT) {
        float4 v = l4[i];
        mx = fmaxf(mx, fmaxf(fmaxf(v.x, v.y), fmaxf(v.z, v.w)));
        s += __expf(v.x * invT) + __expf(v.y * invT) + __expf(v.z * invT) + __expf(v.w * invT);
    }
    s += s2;
    for (int t = (V4 << 2) + tid; t < V; t += NT) {
        float x = lrow[t];
        mx = fmaxf(mx, x);
        s += __expf(x * invT);
    }
    s = warp_red_sum(s);
    if (lane == 0) wred[wid] = s;
    __syncthreads();
    if (wid == 0) { float t = warp_red_sum(wred[lane]); if (lane == 0) s_S = t; }
    __syncthreads();
    mx = warp_red_max(mx);
    if (lane == 0) wred[wid] = mx;
    __syncthreads();
    if (wid == 0) {
        float t = warp_red_max(wred[lane]);
        if (lane == 0) {
            float mxT = t * invT;
            s_shift = (mxT > 80.f || !isfinite(s_S)) ? mxT : 0.f;
        }
    }
    __syncthreads();
    const float shift = s_shift;
    if (shift != 0.f) {            // rare overflow-safe recompute (precise path)
        s = 0.f;
        for (int t = tid; t < V; t += NT) s += expf(lrow[t] * invT - shift);
        s = warp_red_sum(s);
        if (lane == 0) wred[wid] = s;
        __syncthreads();
        if (wid == 0) { float t = warp_red_sum(wred[lane]); if (lane == 0) s_S = t; }
        __syncthreads();
    }

    // ---- Phase B: 16k-point subsample histogram (floor x>2) + parallel suffix pick
    if (V > CAP) {
        for (int t = tid; t < NBINS; t += NT) hist[t] = 0;
        __syncthreads();
        int step4 = V4 / 4096; if (step4 < 1) step4 = 1;
        int ns4 = V4 / step4; if (ns4 > 4096) ns4 = 4096;
        int subN = ns4 * 4;
        for (int j = tid; j < ns4; j += NT) {
            float4 v = l4[(size_t)j * step4];
            if (v.x > 2.0f) atomicAdd(&hist[bin_of(v.x)], 1);
            if (v.y > 2.0f) atomicAdd(&hist[bin_of(v.y)], 1);
            if (v.z > 2.0f) atomicAdd(&hist[bin_of(v.z)], 1);
            if (v.w > 2.0f) atomicAdd(&hist[bin_of(v.w)], 1);
        }
        if (tid == 0) s_bt = 1024;      // default: over-gather -> verified fallback
        __syncthreads();
        // target expected true count ~1.55*need (>=4 sigma both sides of [1024,2048])
        int tgt = (int)(((long long)need * 31LL * subN) / (20LL * (long long)V));
        if (tgt < 1) tgt = 1;
        int b = 2047 - tid;                       // bins 1088..2047 across 960 threads
        int v = (tid < 960) ? hist[b] : 0;
        int sfx = block_incl_scan_int(v, iwsum, lane, wid);
        if (tid < 960 && sfx >= tgt && sfx - v < tgt) s_bt = b;
        __syncthreads();
    }

    // ---- Phase C: gather candidates (L2-resident re-read), verify, rare fallback
    int attempt = 0, cnt = 0;
    for (;;) {
        if (V <= CAP) {
            for (int t = tid; t < V; t += NT) {
                g_cval[row * CAP + t] = lrow[t];
                g_cidx[row * CAP + t] = t;
            }
            cnt = V;
            break;
        }
        if (tid == 0) s_cnt = 0;
        __syncthreads();
        const float xthr = (float)s_bt * 0.03125f - 32.0f;
        int ii = tid;
        for (; ii + NT < V4; ii += 2 * NT) {
            float4 v0 = l4[ii];
            float4 v1 = l4[ii + NT];
            #pragma unroll
            for (int c = 0; c < 4; c++) {
                float x = (c == 0) ? v0.x : (c == 1) ? v0.y : (c == 2) ? v0.z : v0.w;
                if (x >= xthr) {
                    int pos = atomicAdd(&s_cnt, 1);
                    if (pos < CAP) { g_cval[row * CAP + pos] = x; g_cidx[row * CAP + pos] = (ii << 2) + c; }
                }
            }
            #pragma unroll
            for (int c = 0; c < 4; c++) {
                float x = (c == 0) ? v1.x : (c == 1) ? v1.y : (c == 2) ? v1.z : v1.w;
                if (x >= xthr) {
                    int pos = atomicAdd(&s_cnt, 1);
                    if (pos < CAP) { g_cval[row * CAP + pos] = x; g_cidx[row * CAP + pos] = ((ii + NT) << 2) + c; }
                }
            }
        }
        for (; ii < V4; ii += NT) {
            float4 v = l4[ii];
            #pragma unroll
            for (int c = 0; c < 4; c++) {
                float x = (c == 0) ? v.x : (c == 1) ? v.y : (c == 2) ? v.z : v.w;
                if (x >= xthr) {
                    int pos = atomicAdd(&s_cnt, 1);
                    if (pos < CAP) { g_cval[row * CAP + pos] = x; g_cidx[row * CAP + pos] = (ii << 2) + c; }
                }
            }
        }
        for (int t = (V4 << 2) + tid; t < V; t += NT) {
            float x = lrow[t];
            if (x >= xthr) {
                int pos = atomicAdd(&s_cnt, 1);
                if (pos < CAP) { g_cval[row * CAP + pos] = x; g_cidx[row * CAP + pos] = t; }
            }
        }
        __syncthreads();
        cnt = s_cnt;
        if ((cnt >= need && cnt <= CAP) || attempt) break;
        // FALLBACK (~never): exact full histogram, conservative threshold
        for (int t = tid; t < NBINS; t += NT) hist[t] = 0;
        __syncthreads();
        for (int t = tid; t < V; t += NT) atomicAdd(&hist[bin_of(lrow[t])], 1);
        __syncthreads();
        if (tid == 0) {
            int acc = 0, bt2 = 0;
            for (int b = NBINS - 1; b >= 0; b--) {
                int na = acc + hist[b];
                if (na >= need) { bt2 = (na <= CAP) ? b : (b + 1); break; }
                acc = na;
            }
            s_bt = bt2 > 0 ? bt2 - 1 : 0;   // one-bin margin for float-edge compare
        }
        __syncthreads();
        attempt = 1;
    }
    if (tid == 0) {
        g_cnt[row]   = cnt < CAP ? cnt : CAP;
        g_sum[row]   = s_S;
        g_shift[row] = shift;
    }
}

// ---------------- Sort helpers ----------------
__device__ __forceinline__ unsigned long long shfl_xor_u64(unsigned long long v, int m) {
    unsigned lo = (unsigned)v, hi = (unsigned)(v >> 32);
    lo = __shfl_xor_sync(0xffffffffu, lo, m);
    hi = __shfl_xor_sync(0xffffffffu, hi, m);
    return ((unsigned long long)hi << 32) | lo;
}
// Register compare-exchange via shuffle: element index e, stage k, step j (<=16)
__device__ __forceinline__ unsigned long long ce_shfl(unsigned long long r, int e, int k, int j) {
    unsigned long long p = shfl_xor_u64(r, j);
    bool keepMax = (((e & k) == 0) == ((e & j) == 0));   // descending-block low keeps max
    bool pG = p > r;
    return (keepMax == pG) ? p : r;
}
__device__ __forceinline__ void ce_sh(unsigned long long* sk, int i, int j, int k) {
    unsigned long long x = sk[i], y = sk[i + j];
    if (((i & k) == 0) ? (x < y) : (x > y)) { sk[i] = y; sk[i + j] = x; }
}

// ---------------- Kernel 2: zero outputs + sort + masks + sample + scatter ----
__global__ void __launch_bounds__(NT) k_sample(const float* __restrict__ temps,
                                               const int*   __restrict__ top_ks,
                                               const float* __restrict__ top_ps,
                                               const float* __restrict__ min_ps,
                                               const float* __restrict__ u,
                                               float* __restrict__ out,
                                               int V, int B, int tokens_first)
{
    const int row = blockIdx.x;
    const int tid = threadIdx.x;
    const int lane = tid & 31, wid = tid >> 5;
    __shared__ unsigned long long sk[CAP];
    __shared__ float wsum[32];
    __shared__ float sh_p0, sh_tot;

    // Zero this row's output slice FIRST: streaming stores drain under the sort.
    float* probs_out = tokens_first ? (out + B) : out;
    float* prow = probs_out + (size_t)row * V;
    if (((B & 3) == 0 || !tokens_first) && (V & 3) == 0) {
        float4* p4 = (float4*)prow;
        const float4 z4 = make_float4(0.f, 0.f, 0.f, 0.f);
        const int V4 = V >> 2;
        for (int i = tid; i < V4; i += NT) __stcs(p4 + i, z4);
    } else {
        for (int i = tid; i < V; i += NT) __stcs(prow + i, 0.f);
    }

    const int C = g_cnt[row];

    if (C <= 2048) {
        // -------- Hybrid bitonic sort, N=2048, thread t owns {t, t+1024} --------
        unsigned long long a = 0ULL, b = 0ULL;
        if (tid < C) {
            unsigned fb = __float_as_uint(g_cval[row * CAP + tid]);
            unsigned mu = (fb & 0x80000000u) ? ~fb : (fb | 0x80000000u);
            a = ((unsigned long long)mu << 32) | (0xFFFFFFFFu - (unsigned)g_cidx[row * CAP + tid]);
        }
        if (tid + 1024 < C) {
            unsigned fb = __float_as_uint(g_cval[row * CAP + tid + 1024]);
            unsigned mu = (fb & 0x80000000u) ? ~fb : (fb | 0x80000000u);
            b = ((unsigned long long)mu << 32) | (0xFFFFFFFFu - (unsigned)g_cidx[row * CAP + tid + 1024]);
        }
        // Stages k=2..32: fully in registers (shfl), no barriers
        #pragma unroll
        for (int k = 2; k <= 32; k <<= 1) {
            #pragma unroll
            for (int j = k >> 1; j >= 1; j >>= 1) {
                a = ce_shfl(a, tid, k, j);
                b = ce_shfl(b, tid + 1024, k, j);
            }
        }
        // Stages k=64..1024: j>=32 via shared, j<=16 via shfl
        for (int k = 64; k <= 1024; k <<= 1) {
            sk[tid] = a; sk[tid + 1024] = b;
            __syncthreads();
            for (int j = k >> 1; j >= 32; j >>= 1) {
                int i = ((tid & ~(j - 1)) << 1) | (tid & (j - 1));
                ce_sh(sk, i, j, k);
                __syncthreads();
            }
            a = sk[tid]; b = sk[tid + 1024];
            #pragma unroll
            for (int j = 16; j >= 1; j >>= 1) {
                a = ce_shfl(a, tid, k, j);
                b = ce_shfl(b, tid + 1024, k, j);
            }
        }
        // Stage k=2048: j=1024 in-thread, j=512..32 shared, j<=16 shfl
        if (a < b) { unsigned long long t2 = a; a = b; b = t2; }
        sk[tid] = a; sk[tid + 1024] = b;
        __syncthreads();
        for (int j = 512; j >= 32; j >>= 1) {
            int i = ((tid & ~(j - 1)) << 1) | (tid & (j - 1));
            ce_sh(sk, i, j, 2048);
            __syncthreads();
        }
        a = sk[tid]; b = sk[tid + 1024];
        #pragma unroll
        for (int j = 16; j >= 1; j >>= 1) {
            a = ce_shfl(a, tid, 2048, j);
            b = ce_shfl(b, tid + 1024, 2048, j);
        }
        sk[tid] = a;            // only ranks < 1024 matter downstream
        __syncthreads();
    } else {
        // -------- Generic fallback: all-shared bitonic on 4096 (rare) --------
        const int npow2 = CAP;
        const int NCE = npow2 >> 1;
        for (int i = tid; i < npow2; i += NT) {
            unsigned long long key = 0ULL;
            if (i < C) {
                unsigned fb = __float_as_uint(g_cval[row * CAP + i]);
                unsigned mu = (fb & 0x80000000u) ? ~fb : (fb | 0x80000000u);
                key = ((unsigned long long)mu << 32) | (0xFFFFFFFFu - (unsigned)g_cidx[row * CAP + i]);
            }
            sk[i] = key;
        }
        __syncthreads();
        for (int k = 2; k <= npow2; k <<= 1) {
            int j = k >> 1;
            for (; j >= 64; j >>= 1) {
                for (int c = tid; c < NCE; c += NT) {
                    int i = ((c & ~(j - 1)) << 1) | (c & (j - 1));
                    ce_sh(sk, i, j, k);
                }
                __syncthreads();
            }
            for (; j >= 1; j >>= 1) {
                for (int c = tid; c < NCE; c += NT) {
                    int i = ((c & ~(j - 1)) << 1) | (c & (j - 1));
                    ce_sh(sk, i, j, k);
                }
                __syncwarp();
            }
            __syncthreads();
        }
    }

    // ---- Per-rank prob (only first NT ranks can survive: top_k < 1024) ----
    const float invT  = 1.0f / temps[row];
    const float S     = g_sum[row];
    const float shift = g_shift[row];
    float p = 0.f;
    int   myidx = 0;
    if (tid < C) {
        unsigned long long key = sk[tid];
        unsigned mu = (unsigned)(key >> 32);
        unsigned fb = (mu & 0x80000000u) ? (mu ^ 0x80000000u) : ~mu;
        p = expf(__uint_as_float(fb) * invT - shift) / S;
        myidx = (int)(0xFFFFFFFFu - (unsigned)(key & 0xFFFFFFFFu));
    }
    if (tid == 0) sh_p0 = p;

    float cumincl = block_incl_scan(p, wsum, lane, wid);   // pre-mask cumsum

    const int   tk  = top_ks[row];
    const float tp  = top_ps[row];
    const float thr = sh_p0 * min_ps[row];
    float q = p;
    if (tid >= tk)        q = 0.f;   // top-k
    if (cumincl - q > tp) q = 0.f;   // top-p (cumsum computed pre-mask)
    if (q < thr)          q = 0.f;   // min-p

    float cq = block_incl_scan(q, wsum, lane, wid);        // post-mask CDF numerator
    if (tid == NT - 1) sh_tot = cq;
    __syncthreads();
    const float tot  = sh_tot;
    const float uval = u[row];

    int rank = __syncthreads_count((cq / tot < uval) ? 1 : 0);
    if (rank > NT - 1) rank = NT - 1;
    if (rank > V - 1) rank = V - 1;

    if (tid == 0 && tokens_first) {
        unsigned long long key = sk[rank];
        out[row] = (float)(int)(0xFFFFFFFFu - (unsigned)(key & 0xFFFFFFFFu));
    }
    if (q > 0.f) {
        prow[myidx] = q / tot;     // ordered after zero-stores by the barriers above
    }
}

extern "C" void kernel_launch(void* const* d_in, const int* in_sizes, int n_in,
                              void* d_out, int out_size)
{
    const float* logits = (const float*)d_in[0];
    const float* temps  = (const float*)d_in[1];
    const int*   topks  = (const int*)  d_in[2];
    const float* topps  = (const float*)d_in[3];
    const float* minps  = (const float*)d_in[4];
    const float* u      = (const float*)d_in[5];

    const int B = in_sizes[1];
    const int V = in_sizes[0] / B;
    float* out = (float*)d_out;
    int tokens_first = (out_size == B + B * V) ? 1 : 0;

    k_stats <<<B, NT>>>(logits, temps, V);
    k_sample<<<B, NT>>>(temps, topks, topps, minps, u, out, V, B, tokens_first);
}